// round 12
// baseline (speedup 1.0000x reference)
#include <cuda_runtime.h>

// predictor_interp2d: nearest-neighbor gather from N=1024 points onto a 256x256 grid.
// d_in[0] = R_pc  [B=2, C=4, N=1024] float32
// d_in[1] = XY_pc [B=2, 2, N=1024]   float32
// d_out   = R_grd [B=2, C=4, 256, 256] float32
//
// Single fused kernel (R9 base), 128 blocks x 1024 threads. Each block owns a
// 32x32-cell region, redundantly bins all 1024 points of its batch into a
// block-local 32x32 CSR in shared memory, stages R in smem. Fast path: each
// thread scans a quadrant-aligned 4x4-bin window (shifted toward its cell;
// interior margin >= 1.5/32, miss prob ~8.5e-4/cell) as 4 flat CSR row
// segments, with TWO independent packed-key accumulators for ILP. A
// rounding-safe bound against the actual window faces certifies the result;
// rare failures fall back to expanding rings from r=2 (certified radius 1).
//
// Argmin key = (ordered_uint(d2) << 32) | point_index, u64 min == (min d2,
// then min index) == jnp.argmin first-min semantics. d2 uses the EXACT
// reference arithmetic (bit-matched since R2) -> bit-identical output,
// scatter order irrelevant.

#define NPTS  1024
#define NB    32
#define BINW  0.03125f

__global__ __launch_bounds__(1024, 1)
void nn_fused(const float* __restrict__ XY,
              const float* __restrict__ R,
              float* __restrict__ out) {
    __shared__ float4 spts[NPTS];        // {px, py, s, index-as-bits}, bin-ordered
    __shared__ int    soff[NB*NB + 1];   // CSR offsets
    __shared__ int    scnt[NB*NB];       // bin counts
    __shared__ int    scur[NB*NB];       // scatter cursors
    __shared__ int    swsum[32];         // per-warp scan partials
    __shared__ float  sR[4 * NPTS];      // staged field values (16 KB)

    const int t    = threadIdx.x;
    const int b    = blockIdx.x >> 6;            // 64 regions per batch
    const int quad = blockIdx.x & 63;            // 8x8 regions of 32x32 cells

    // ---- Phase 1: block-local binning of all 1024 points (1 per thread) ----
    const float* xy = XY + b * (2 * NPTS);
    const float* Rb = R  + b * (4 * NPTS);

    scnt[t] = 0;
    scur[t] = 0;

    // Stage R to smem (coalesced; latency overlapped with binning below).
    #pragma unroll
    for (int c = 0; c < 4; ++c)
        sR[c * NPTS + t] = Rb[c * NPTS + t];

    __syncthreads();

    const float x = xy[t];
    const float y = xy[NPTS + t];
    const int bxx = min(max((int)(x * 32.0f), 0), NB - 1);
    const int byy = min(max((int)(y * 32.0f), 0), NB - 1);
    const int pbin = byy * NB + bxx;
    atomicAdd(&scnt[pbin], 1);
    __syncthreads();

    // 1024-wide exclusive scan: warp shfl scan + 32-partial warp-0 scan.
    {
        const int v = scnt[t];
        int incl = v;
        #pragma unroll
        for (int d = 1; d < 32; d <<= 1) {
            const int n = __shfl_up_sync(0xffffffffu, incl, d);
            if ((t & 31) >= d) incl += n;
        }
        if ((t & 31) == 31) swsum[t >> 5] = incl;
        __syncthreads();
        if (t < 32) {
            const int w = swsum[t];
            int iw = w;
            #pragma unroll
            for (int d = 1; d < 32; d <<= 1) {
                const int n = __shfl_up_sync(0xffffffffu, iw, d);
                if (t >= d) iw += n;
            }
            swsum[t] = iw - w;                   // exclusive warp base
        }
        __syncthreads();
        soff[t] = incl - v + swsum[t >> 5];      // exclusive prefix for bin t
        if (t == 0) soff[NB*NB] = NPTS;
    }
    __syncthreads();

    {
        const int pos = soff[pbin] + atomicAdd(&scur[pbin], 1);
        // s with the reference's rounding order (mul, mul, add)
        const float s = __fadd_rn(__fmul_rn(x, x), __fmul_rn(y, y));
        spts[pos] = make_float4(x, y, s, __int_as_float(t));
    }
    __syncthreads();

    // ---- Phase 2: NN search ----
    const int sel = t >> 8;
    const int u   = t & 255;
    const int qx  = quad & 7, qy = quad >> 3;
    const int cx  = qx * 32 + (sel & 1) * 16 + (u & 15);
    const int cy  = qy * 32 + (sel >> 1) * 16 + (u >> 4);
    const int cell = cy * 256 + cx;
    const int bx  = cx >> 3;                     // 8 cells per 1/32 bin
    const int by  = cy >> 3;

    const float inv = 1.0f / 256.0f;
    const float gx = ((float)cx + 0.5f) * inv;
    const float gy = ((float)cy + 0.5f) * inv;
    const float g2 = gx * gx + gy * gy;          // geometry bound only

    // Two independent packed-key accumulators (break the serial min chain).
    unsigned long long bk0 = 0xFFFFFFFFFFFFFFFFull;
    unsigned long long bk1 = 0xFFFFFFFFFFFFFFFFull;

    #define EVAL(BK, P)                                                         \
        {                                                                       \
            const float dot = __fmaf_rn((P).y, gy, __fmul_rn((P).x, gx));       \
            const float d   = __fmaf_rn(-2.0f, dot, (P).z);                     \
            unsigned int ub = __float_as_uint(d);                               \
            ub ^= (unsigned int)(((int)ub >> 31)) | 0x80000000u;                \
            const unsigned long long key =                                      \
                ((unsigned long long)ub << 32) | __float_as_uint((P).w);        \
            BK = min(BK, key);                                                  \
        }

    // Fast path: quadrant-aligned 4x4 bin window, clipped; rows CSR-contiguous.
    const int sx  = ((cx & 7) >= 4) ? 1 : 0;     // shift toward the cell
    const int sy  = ((cy & 7) >= 4) ? 1 : 0;
    const int wxa = max(bx - 2 + sx, 0), wxb = min(bx + 1 + sx, NB - 1);
    const int wya = max(by - 2 + sy, 0), wyb = min(by + 1 + sy, NB - 1);
    for (int yb = wya; yb <= wyb; ++yb) {
        const int e0 = soff[yb * NB + wxa];
        const int e1 = soff[yb * NB + wxb + 1];
        #pragma unroll 2
        for (int k = e0; k < e1; ++k) {
            const float4 p = spts[k];
            if (k & 1) EVAL(bk1, p) else EVAL(bk0, p)
        }
    }
    unsigned long long bestk = min(bk0, bk1);

    // Certification bound against the ACTUAL window faces (domain-clipped faces
    // excluded). Unscanned points have computed d2 >= f^2 - g2 - eps; slack
    // 1e-4 >> eps forbids beating OR tying the current winner.
    {
        const float fL = (wxa >= 1)      ? (gx - (float)wxa * BINW)       : 1e30f;
        const float fR = (wxb <= NB - 2) ? ((float)(wxb + 1) * BINW - gx) : 1e30f;
        const float fB = (wya >= 1)      ? (gy - (float)wya * BINW)       : 1e30f;
        const float fT = (wyb <= NB - 2) ? ((float)(wyb + 1) * BINW - gy) : 1e30f;
        const float f  = fminf(fminf(fL, fR), fminf(fB, fT));
        const unsigned int ob = (unsigned int)(bestk >> 32);
        const unsigned int fb = (ob & 0x80000000u) ? (ob ^ 0x80000000u) : ~ob;
        const float best = __uint_as_float(fb);
        const int cont = !(f * f > best + g2 + 1e-4f);       // NaN best -> cont
        if (__any_sync(0xffffffffu, cont)) {
            // Cold path: expanding rings, certified scanned square radius 1
            // (window always contains the centered 3x3). Re-scanning overlap
            // bins is harmless (min is idempotent).
            for (int r = 2; r < NB; ++r) {
                const unsigned int ob2 = (unsigned int)(bestk >> 32);
                const unsigned int fb2 = (ob2 & 0x80000000u) ? (ob2 ^ 0x80000000u) : ~ob2;
                const float best2 = __uint_as_float(fb2);
                const float cL = (bx - (r - 1) >= 1)      ? (gx - (float)(bx - (r - 1)) * BINW) : 1e30f;
                const float cR = (bx + (r - 1) <= NB - 2) ? ((float)(bx + r) * BINW - gx)       : 1e30f;
                const float cB = (by - (r - 1) >= 1)      ? (gy - (float)(by - (r - 1)) * BINW) : 1e30f;
                const float cT = (by + (r - 1) <= NB - 2) ? ((float)(by + r) * BINW - gy)       : 1e30f;
                const float cf = fminf(fminf(cL, cR), fminf(cB, cT));
                const int c2 = !(cf * cf > best2 + g2 + 1e-4f);
                if (!__any_sync(0xffffffffu, c2)) break;     // per-warp exit

                const int x0 = max(bx - r, 0), x1 = min(bx + r, NB - 1);
                const int y0 = max(by - r, 0), y1 = min(by + r, NB - 1);
                for (int yb = y0; yb <= y1; ++yb) {
                    if (yb == by - r || yb == by + r) {
                        const int e0 = soff[yb * NB + x0];
                        const int e1 = soff[yb * NB + x1 + 1];
                        for (int k = e0; k < e1; ++k) {
                            const float4 p = spts[k];
                            EVAL(bestk, p)
                        }
                    } else {
                        if (bx - r >= 0) {
                            const int bb = yb * NB + (bx - r);
                            for (int k = soff[bb]; k < soff[bb + 1]; ++k) {
                                const float4 p = spts[k];
                                EVAL(bestk, p)
                            }
                        }
                        if (bx + r <= NB - 1) {
                            const int bb = yb * NB + (bx + r);
                            for (int k = soff[bb]; k < soff[bb + 1]; ++k) {
                                const float4 p = spts[k];
                                EVAL(bestk, p)
                            }
                        }
                    }
                }
            }
        }
    }
    #undef EVAL

    const int bi = (int)(bestk & 0xFFFFFFFFull);

    // ---- Phase 3: gather 4 channels from smem-staged R ----
    float* ob = out + b * (4 * 65536);
    #pragma unroll
    for (int c = 0; c < 4; ++c)
        ob[c * 65536 + cell] = sR[c * NPTS + bi];
}

extern "C" void kernel_launch(void* const* d_in, const int* in_sizes, int n_in,
                              void* d_out, int out_size) {
    const float* R  = (const float*)d_in[0];   // [2,4,1024]
    const float* XY = (const float*)d_in[1];   // [2,2,1024]
    float* out = (float*)d_out;                // [2,4,256,256]

    nn_fused<<<128, 1024>>>(XY, R, out);
}

// round 13
// speedup vs baseline: 1.2657x; 1.2657x over previous
#include <cuda_runtime.h>

// predictor_interp2d: nearest-neighbor gather from N=1024 points onto a 256x256 grid.
// d_in[0] = R_pc  [B=2, C=4, N=1024] float32
// d_in[1] = XY_pc [B=2, 2, N=1024]   float32
// d_out   = R_grd [B=2, C=4, 256, 256] float32
//
// BEST MEASURED CONFIG (R9): single fused kernel, one 1024-thread block per
// 32x32-cell region (128 blocks, one wave). Each block redundantly bins all
// 1024 points of its batch into a block-local 32x32 CSR in shared memory
// (1 point/thread, 1024-wide two-level scan), stages the R table in smem,
// then each thread scans the clipped 5x5 bin neighborhood of its cell
// (coverage radius 2/32 = 0.0625, miss prob ~3.5e-6/cell) as <=5 flat CSR
// segments with warp-uniform bounds, falling back to a rounding-safe
// expanding-ring loop for the rare remainder.
//
// Argmin is branch-free: key = (ordered_uint(d2) << 32) | point_index, reduced
// with u64 min == (min d2, then min index) == jnp.argmin first-min semantics.
// d2 uses the EXACT reference arithmetic (bit-matched since R2), so the result
// is bit-identical and bin scatter order is irrelevant.

#define NPTS  1024
#define NB    32
#define BINW  0.03125f

__global__ __launch_bounds__(1024, 1)
void nn_fused(const float* __restrict__ XY,
              const float* __restrict__ R,
              float* __restrict__ out) {
    __shared__ float4 spts[NPTS];        // {px, py, s, index-as-bits}, bin-ordered
    __shared__ int    soff[NB*NB + 1];   // CSR offsets (1025 ints)
    __shared__ int    scnt[NB*NB];       // bin counts
    __shared__ int    scur[NB*NB];       // scatter cursors
    __shared__ int    swsum[32];         // per-warp scan partials
    __shared__ float  sR[4 * NPTS];      // staged field values (16 KB)

    const int t    = threadIdx.x;
    const int b    = blockIdx.x >> 6;            // 64 regions per batch
    const int quad = blockIdx.x & 63;            // 8x8 regions of 32x32 cells

    // ---- Phase 1: block-local binning of all 1024 points (1 per thread) ----
    const float* xy = XY + b * (2 * NPTS);
    const float* Rb = R  + b * (4 * NPTS);

    scnt[t] = 0;
    scur[t] = 0;

    // Stage R to smem (coalesced; latency overlapped with binning below).
    #pragma unroll
    for (int c = 0; c < 4; ++c)
        sR[c * NPTS + t] = Rb[c * NPTS + t];

    __syncthreads();

    const float x = xy[t];
    const float y = xy[NPTS + t];
    const int bxx = min(max((int)(x * 32.0f), 0), NB - 1);
    const int byy = min(max((int)(y * 32.0f), 0), NB - 1);
    const int pbin = byy * NB + bxx;
    atomicAdd(&scnt[pbin], 1);
    __syncthreads();

    // 1024-wide exclusive scan: warp shfl scan + 32-partial warp-0 scan.
    {
        const int v = scnt[t];
        int incl = v;
        #pragma unroll
        for (int d = 1; d < 32; d <<= 1) {
            const int n = __shfl_up_sync(0xffffffffu, incl, d);
            if ((t & 31) >= d) incl += n;
        }
        if ((t & 31) == 31) swsum[t >> 5] = incl;
        __syncthreads();
        if (t < 32) {
            const int w = swsum[t];
            int iw = w;
            #pragma unroll
            for (int d = 1; d < 32; d <<= 1) {
                const int n = __shfl_up_sync(0xffffffffu, iw, d);
                if (t >= d) iw += n;
            }
            swsum[t] = iw - w;                   // exclusive warp base
        }
        __syncthreads();
        soff[t] = incl - v + swsum[t >> 5];      // exclusive prefix for bin t
        if (t == 0) soff[NB*NB] = NPTS;
    }
    __syncthreads();

    {
        const int pos = soff[pbin] + atomicAdd(&scur[pbin], 1);
        // s with the reference's rounding order (mul, mul, add)
        const float s = __fadd_rn(__fmul_rn(x, x), __fmul_rn(y, y));
        spts[pos] = make_float4(x, y, s, __int_as_float(t));
    }
    __syncthreads();

    // ---- Phase 2: NN search ----
    // Region = 2x2 super-tile of 16-cell bins: cells [qx*32, qx*32+31] x [qy*32 ..].
    // Thread u (0..255) within tile sel (0..3); each warp = 2 cell-rows of one
    // 16x16 tile -> home bin is warp-uniform.
    const int sel = t >> 8;
    const int u   = t & 255;
    const int qx  = quad & 7, qy = quad >> 3;
    const int cx  = qx * 32 + (sel & 1) * 16 + (u & 15);
    const int cy  = qy * 32 + (sel >> 1) * 16 + (u >> 4);
    const int cell = cy * 256 + cx;
    const int bx  = cx >> 3;                     // 8 cells per 1/32 bin
    const int by  = cy >> 3;

    const float inv = 1.0f / 256.0f;
    const float gx = ((float)cx + 0.5f) * inv;
    const float gy = ((float)cy + 0.5f) * inv;
    const float g2 = gx * gx + gy * gy;          // geometry bound only

    // Packed (ordered d2, index) key; u64 min == lexicographic first-min.
    unsigned long long bestk = 0xFFFFFFFFFFFFFFFFull;

    #define SCAN_RANGE(E0, E1)                                                  \
        _Pragma("unroll 2")                                                     \
        for (int k = (E0); k < (E1); ++k) {                                     \
            const float4 p = spts[k];                                           \
            const float dot = __fmaf_rn(p.y, gy, __fmul_rn(p.x, gx));           \
            const float d   = __fmaf_rn(-2.0f, dot, p.z);                       \
            unsigned int ub = __float_as_uint(d);                               \
            ub ^= (unsigned int)(((int)ub >> 31)) | 0x80000000u;                \
            const unsigned long long key =                                      \
                ((unsigned long long)ub << 32) | __float_as_uint(p.w);          \
            bestk = min(bestk, key);                                            \
        }

    // Fast path: clipped 5x5 bin neighborhood == scanned square radius 2
    // (coverage radius >= 2/32 = 0.0625). Rows are CSR-contiguous.
    {
        const int xx0 = max(bx - 2, 0), xx1 = min(bx + 2, NB - 1);
        const int yy0 = max(by - 2, 0), yy1 = min(by + 2, NB - 1);
        for (int yb = yy0; yb <= yy1; ++yb) {
            const int e0 = soff[yb * NB + xx0];
            const int e1 = soff[yb * NB + xx1 + 1];
            SCAN_RANGE(e0, e1)
        }
    }

    // Cold path: expanding rings r>=3 with rounding-safe termination.
    for (int r = 3; r < NB; ++r) {
        // Decode current best d2 (NaN if nothing scanned yet -> keep going).
        const unsigned int ob = (unsigned int)(bestk >> 32);
        const unsigned int fb = (ob & 0x80000000u) ? (ob ^ 0x80000000u) : ~ob;
        const float best = __uint_as_float(fb);
        // Distance to boundary of scanned square [bx-(r-1), bx+(r-1)]^2;
        // domain-edge faces excluded. Unscanned points have computed
        // d2 >= f^2 - g2 - eps; slack 1e-4 >> eps forbids beating OR tying,
        // so extra rings scanned for warp-mates can't change this thread.
        const float fL = (bx - (r - 1) >= 1)      ? (gx - (float)(bx - (r - 1)) * BINW) : 1e30f;
        const float fR = (bx + (r - 1) <= NB - 2) ? ((float)(bx + r) * BINW - gx)       : 1e30f;
        const float fB = (by - (r - 1) >= 1)      ? (gy - (float)(by - (r - 1)) * BINW) : 1e30f;
        const float fT = (by + (r - 1) <= NB - 2) ? ((float)(by + r) * BINW - gy)       : 1e30f;
        const float f  = fminf(fminf(fL, fR), fminf(fB, fT));
        const int cont = !(f * f > best + g2 + 1e-4f);       // NaN best -> cont
        if (!__any_sync(0xffffffffu, cont)) break;           // per-warp exit

        const int x0 = max(bx - r, 0), x1 = min(bx + r, NB - 1);
        const int y0 = max(by - r, 0), y1 = min(by + r, NB - 1);
        for (int yb = y0; yb <= y1; ++yb) {
            if (yb == by - r || yb == by + r) {
                const int e0 = soff[yb * NB + x0];
                const int e1 = soff[yb * NB + x1 + 1];
                SCAN_RANGE(e0, e1)
            } else {
                if (bx - r >= 0) {
                    const int bb = yb * NB + (bx - r);
                    SCAN_RANGE(soff[bb], soff[bb + 1])
                }
                if (bx + r <= NB - 1) {
                    const int bb = yb * NB + (bx + r);
                    SCAN_RANGE(soff[bb], soff[bb + 1])
                }
            }
        }
    }
    #undef SCAN_RANGE

    const int bi = (int)(bestk & 0xFFFFFFFFull);

    // ---- Phase 3: gather 4 channels from smem-staged R ----
    float* ob = out + b * (4 * 65536);
    #pragma unroll
    for (int c = 0; c < 4; ++c)
        ob[c * 65536 + cell] = sR[c * NPTS + bi];
}

extern "C" void kernel_launch(void* const* d_in, const int* in_sizes, int n_in,
                              void* d_out, int out_size) {
    const float* R  = (const float*)d_in[0];   // [2,4,1024]
    const float* XY = (const float*)d_in[1];   // [2,2,1024]
    float* out = (float*)d_out;                // [2,4,256,256]

    nn_fused<<<128, 1024>>>(XY, R, out);
}